// round 17
// baseline (speedup 1.0000x reference)
#include <cuda_runtime.h>
#include <cuda_fp16.h>
#include <cstdint>

// Problem constants
#define B_    16
#define CC    256
#define HW    4096
#define NTOK  65536
#define NE    1024
#define D     256
#define ZQ_ELEMS (NTOK * CC)
#define LOSS_OFF ZQ_ELEMS
#define CLS_OFF  (ZQ_ELEMS + 1)
#define IDX_OFF  (ZQ_ELEMS + 2)
#define GRID_C 2048

#define MARGIN_I8 3.0f   // ~10x screening-error std; rescore pass stays exact
#define KCAND  64        // per-token candidate cap

// Pass-1 tiling: CTA = 128 tokens x NE codes; chunk = FULL j-tile (64 codes x K=256)
// Warp tile m32 x n32 (4 m-blocks x 2 n-blocks = 8 warps); imma m16n8k32
#define TM   128
#define JT   64
#define NCHUNK 16            // 16 j-tiles, one barrier pair each (was 64)

// Pass-1 smem layout (bytes)
#define AS_PITCH_B 272       // int8 bytes per token row (256 + 16 pad)
#define AS_PITCH_W 68        // words
#define OFF_AS 0             // int8 As[128][272] = 34816
#define BS_PITCH_B 272       // int8 bytes per code row (256 + 16 pad); stride=4 banks
#define BS_PITCH_W 68
#define BS_SZ  17408         // 64 * 272 per stage
#define OFF_BS 34816         // two cp.async stages -> +34816
#define OFF_CN 69632         // float cn[1024]
#define OFF_CM 73728         // float cmax[1024]
#define OFF_FT 77824         // float ft[128]  (-2*mz/16129)
#define OFF_QS 78336         // float qs[128]  (127/mz)
#define OFF_MZP 78848        // float mzpart[8][128]
#define OFF_CNT 82944        // int cnt[128]
#define OFF_CAND 83456       // ushort cand[128][KCAND]
#define P1_SMEM (OFF_CAND + TM * KCAND * 2)   // 99840 -> 2 CTAs/SM

// Scratch (static device arrays are the sanctioned workaround)
__device__ int            g_cnt[NTOK];
__device__ unsigned short g_cand[(size_t)NTOK * KCAND];   // 8 MB
__device__ int            g_idx[NTOK];
__device__ float          g_cnorm[NE];
__device__ float          g_cmax[NE];
__device__ float          g_partial[GRID_C];
__device__ int8_t         g_cbi8[(size_t)NE * D];         // per-row int8 codebook

// ---------------------------------------------------------------------------
// helpers
// ---------------------------------------------------------------------------
__device__ __forceinline__ uint32_t smem_u32(const void* p) {
    uint32_t a;
    asm("{ .reg .u64 t; cvta.to.shared.u64 t, %1; cvt.u32.u64 %0, t; }"
        : "=r"(a) : "l"(p));
    return a;
}
__device__ __forceinline__ void mma_i8(int& d0, int& d1, int& d2, int& d3,
                                       uint32_t a0, uint32_t a1, uint32_t a2, uint32_t a3,
                                       uint32_t b0, uint32_t b1) {
    asm volatile(
        "mma.sync.aligned.m16n8k32.row.col.s32.s8.s8.s32 "
        "{%0,%1,%2,%3}, {%4,%5,%6,%7}, {%8,%9}, {%0,%1,%2,%3};\n"
        : "+r"(d0), "+r"(d1), "+r"(d2), "+r"(d3)
        : "r"(a0), "r"(a1), "r"(a2), "r"(a3), "r"(b0), "r"(b1));
}
__device__ __forceinline__ void cp_async16(uint32_t dst, const void* src) {
    asm volatile("cp.async.cg.shared.global [%0], [%1], 16;"
                 :: "r"(dst), "l"(src) : "memory");
}
#define CP_COMMIT() asm volatile("cp.async.commit_group;" ::: "memory")
#define CP_WAIT0()  asm volatile("cp.async.wait_group 0;" ::: "memory")

// ---------------------------------------------------------------------------
// Kernel 1: per-code norms, absmax, and int8-quantized codebook
// ---------------------------------------------------------------------------
__global__ void __launch_bounds__(256) cnorm_kernel(const float* __restrict__ cb) {
    int row  = blockIdx.x * 8 + (threadIdx.x >> 5);
    int lane = threadIdx.x & 31;
    const float* p = cb + (size_t)row * D;
    float v[8];
    float s = 0.f, m = 0.f;
    #pragma unroll
    for (int u = 0; u < 8; u++) {
        v[u] = p[lane + 32 * u];
        s = fmaf(v[u], v[u], s);
        m = fmaxf(m, fabsf(v[u]));
    }
    #pragma unroll
    for (int o = 16; o; o >>= 1) {
        s += __shfl_xor_sync(0xffffffffu, s, o);
        m = fmaxf(m, __shfl_xor_sync(0xffffffffu, m, o));
    }
    m = fmaxf(m, 1e-20f);
    if (lane == 0) { g_cnorm[row] = s; g_cmax[row] = m; }
    float qsc = 127.0f / m;
    #pragma unroll
    for (int u = 0; u < 8; u++)
        g_cbi8[(size_t)row * D + lane + 32 * u] = (int8_t)__float2int_rn(v[u] * qsc);
}

// ---------------------------------------------------------------------------
// Kernel 2 (pass 1): int8 IMMA screening + fused candidate selection.
// Chunk = full j-tile (64 codes x K=256): 16 barrier pairs total (4x fewer),
// 64 IMMA/warp of tensor work per barrier window. Per-token / per-code
// scales; d_approx = cn[j] + ft[t]*cm[j]*S_int. Margin-rescore keeps the
// final argmin exact.
// ---------------------------------------------------------------------------
__global__ void __launch_bounds__(256, 2) dist_kernel(const float* __restrict__ z) {
    extern __shared__ char smem[];
    int8_t*         As8   = (int8_t*)(smem + OFF_AS);
    uint32_t*       As_u  = (uint32_t*)(smem + OFF_AS);
    float*          cnS   = (float*)(smem + OFF_CN);
    float*          cmS   = (float*)(smem + OFF_CM);
    float*          ftS   = (float*)(smem + OFF_FT);
    float*          qsS   = (float*)(smem + OFF_QS);
    float*          mzp   = (float*)(smem + OFF_MZP);
    int*            sCnt  = (int*)(smem + OFF_CNT);
    unsigned short* sCand = (unsigned short*)(smem + OFF_CAND);

    const int tid  = threadIdx.x;
    const int w    = tid >> 5;
    const int lane = tid & 31;
    const int r    = lane >> 2;      // row-in-frag 0..7
    const int q    = lane & 3;       // quad column 0..3

    const int mbase = (w & 3) * 32;  // warp's 32-token block
    const int nblk  = w >> 2;        // warp's 32-code half of the j-tile

    const int n0  = blockIdx.x * TM;
    const int b   = n0 >> 12;
    const int rem = n0 & (HW - 1);
    const float* zb = z + (size_t)b * CC * HW + rem;

    // ---- A staging pass 1: per-token absmax ----
    const int t4 = (tid & 31) * 4;   // this thread's 4 tokens
    float m4[4] = {0.f, 0.f, 0.f, 0.f};
    #pragma unroll 8
    for (int l = 0; l < 32; l++) {
        int k = w + 8 * l;
        float4 v = *(const float4*)(zb + (size_t)k * HW + t4);
        m4[0] = fmaxf(m4[0], fabsf(v.x));
        m4[1] = fmaxf(m4[1], fabsf(v.y));
        m4[2] = fmaxf(m4[2], fabsf(v.z));
        m4[3] = fmaxf(m4[3], fabsf(v.w));
    }
    #pragma unroll
    for (int j = 0; j < 4; j++) mzp[w * 128 + t4 + j] = m4[j];
    for (int i = tid; i < NE; i += 256) { cnS[i] = g_cnorm[i]; cmS[i] = g_cmax[i]; }
    for (int i = tid; i < TM; i += 256) sCnt[i] = 0;
    __syncthreads();

    if (tid < TM) {
        float mz = 0.f;
        #pragma unroll
        for (int ww = 0; ww < 8; ww++) mz = fmaxf(mz, mzp[ww * 128 + tid]);
        mz = fmaxf(mz, 1e-20f);
        ftS[tid] = -2.0f * mz / 16129.0f;
        qsS[tid] = 127.0f / mz;
    }
    __syncthreads();

    // ---- A staging pass 2: quantize (z re-read is L2-hot) ----
    {
        float q0 = qsS[t4], q1 = qsS[t4 + 1], q2 = qsS[t4 + 2], q3 = qsS[t4 + 3];
        #pragma unroll 8
        for (int l = 0; l < 32; l++) {
            int k = w + 8 * l;
            float4 v = *(const float4*)(zb + (size_t)k * HW + t4);
            As8[(t4 + 0) * AS_PITCH_B + k] = (int8_t)__float2int_rn(v.x * q0);
            As8[(t4 + 1) * AS_PITCH_B + k] = (int8_t)__float2int_rn(v.y * q1);
            As8[(t4 + 2) * AS_PITCH_B + k] = (int8_t)__float2int_rn(v.z * q2);
            As8[(t4 + 3) * AS_PITCH_B + k] = (int8_t)__float2int_rn(v.w * q3);
        }
    }

    // ---- B staging: thread -> code row tid>>2, 64B quarter (tid&3) ----
    const int jrow = tid >> 2;
    const int kq   = tid & 3;
    const uint32_t bsBase = smem_u32(smem + OFF_BS);
    const uint32_t bsDst  = (uint32_t)(jrow * BS_PITCH_B + kq * 64);
    {   // chunk 0 = j-tile 0, full K
        const int8_t* src = g_cbi8 + (size_t)jrow * D + kq * 64;
        cp_async16(bsDst + bsBase,      src);
        cp_async16(bsDst + bsBase + 16, src + 16);
        cp_async16(bsDst + bsBase + 32, src + 32);
        cp_async16(bsDst + bsBase + 48, src + 48);
        CP_COMMIT();
    }
    __syncthreads();   // As, scales visible

    int acc[8][4];   // [mt*4+nt][c0..c3]
    #pragma unroll
    for (int i = 0; i < 8; i++)
        #pragma unroll
        for (int c = 0; c < 4; c++) acc[i][c] = 0;

    float curMin[4] = {3.4e38f, 3.4e38f, 3.4e38f, 3.4e38f};  // [mt*2 + rowhalf]

    for (int g = 0; g < NCHUNK; g++) {
        CP_WAIT0();
        __syncthreads();

        if (g + 1 < NCHUNK) {
            const int8_t* src = g_cbi8 + (size_t)((g + 1) * JT + jrow) * D + kq * 64;
            uint32_t dst = bsBase + (uint32_t)(((g + 1) & 1) * BS_SZ) + bsDst;
            cp_async16(dst,      src);
            cp_async16(dst + 16, src + 16);
            cp_async16(dst + 32, src + 32);
            cp_async16(dst + 48, src + 48);
            CP_COMMIT();
        }

        // compute j-tile g: 8 k32 steps
        const uint32_t* Bs = (const uint32_t*)(smem + OFF_BS + (g & 1) * BS_SZ);
        #pragma unroll
        for (int ks = 0; ks < 8; ks++) {
            uint32_t a[2][4];
            #pragma unroll
            for (int mt = 0; mt < 2; mt++) {
                const int base = (mbase + mt * 16 + r) * AS_PITCH_W + ks * 8 + q;
                a[mt][0] = As_u[base];
                a[mt][1] = As_u[base + 8 * AS_PITCH_W];
                a[mt][2] = As_u[base + 4];
                a[mt][3] = As_u[base + 4 + 8 * AS_PITCH_W];
            }
            #pragma unroll
            for (int nt = 0; nt < 4; nt++) {
                const int jn = nblk * 32 + nt * 8 + (lane >> 2);
                uint32_t b0 = Bs[jn * BS_PITCH_W + ks * 8 + q];
                uint32_t b1 = Bs[jn * BS_PITCH_W + ks * 8 + q + 4];
                #pragma unroll
                for (int mt = 0; mt < 2; mt++) {
                    int* d = acc[mt * 4 + nt];
                    mma_i8(d[0], d[1], d[2], d[3],
                           a[mt][0], a[mt][1], a[mt][2], a[mt][3], b0, b1);
                }
            }
        }

        // j-tile end: scale to float, running-min, candidate pushes
        {
            const int jcol0 = g * JT + nblk * 32 + 2 * q;
            float vv[8][4];
            #pragma unroll
            for (int mt = 0; mt < 2; mt++) {
                const int tA = mbase + mt * 16 + r;
                const float fA = ftS[tA], fB = ftS[tA + 8];
                #pragma unroll
                for (int nt = 0; nt < 4; nt++) {
                    int j = jcol0 + nt * 8;
                    float sc0 = cmS[j], sc1 = cmS[j + 1];
                    float c0 = cnS[j],  c1 = cnS[j + 1];
                    int* d = acc[mt * 4 + nt];
                    vv[mt * 4 + nt][0] = fmaf(fA * sc0, (float)d[0], c0);
                    vv[mt * 4 + nt][1] = fmaf(fA * sc1, (float)d[1], c1);
                    vv[mt * 4 + nt][2] = fmaf(fB * sc0, (float)d[2], c0);
                    vv[mt * 4 + nt][3] = fmaf(fB * sc1, (float)d[3], c1);
                    d[0] = d[1] = d[2] = d[3] = 0;
                }
            }
            float mn[4] = {3.4e38f, 3.4e38f, 3.4e38f, 3.4e38f};
            #pragma unroll
            for (int mt = 0; mt < 2; mt++)
                #pragma unroll
                for (int nt = 0; nt < 4; nt++) {
                    float* d = vv[mt * 4 + nt];
                    mn[mt * 2 + 0] = fminf(mn[mt * 2 + 0], fminf(d[0], d[1]));
                    mn[mt * 2 + 1] = fminf(mn[mt * 2 + 1], fminf(d[2], d[3]));
                }
            #pragma unroll
            for (int i = 0; i < 4; i++) {
                mn[i] = fminf(mn[i], __shfl_xor_sync(0xffffffffu, mn[i], 1));
                mn[i] = fminf(mn[i], __shfl_xor_sync(0xffffffffu, mn[i], 2));
                curMin[i] = fminf(curMin[i], mn[i]);
            }
            #pragma unroll
            for (int mt = 0; mt < 2; mt++) {
                const int tA = mbase + mt * 16 + r;
                const int tB = tA + 8;
                const float thrA = curMin[mt * 2 + 0] + MARGIN_I8;
                const float thrB = curMin[mt * 2 + 1] + MARGIN_I8;
                #pragma unroll
                for (int nt = 0; nt < 4; nt++) {
                    int j = jcol0 + nt * 8;
                    float* d = vv[mt * 4 + nt];
                    if (d[0] < thrA) {
                        int pos = atomicAdd(&sCnt[tA], 1);
                        if (pos < KCAND) sCand[tA * KCAND + pos] = (unsigned short)j;
                    }
                    if (d[1] < thrA) {
                        int pos = atomicAdd(&sCnt[tA], 1);
                        if (pos < KCAND) sCand[tA * KCAND + pos] = (unsigned short)(j + 1);
                    }
                    if (d[2] < thrB) {
                        int pos = atomicAdd(&sCnt[tB], 1);
                        if (pos < KCAND) sCand[tB * KCAND + pos] = (unsigned short)j;
                    }
                    if (d[3] < thrB) {
                        int pos = atomicAdd(&sCnt[tB], 1);
                        if (pos < KCAND) sCand[tB * KCAND + pos] = (unsigned short)(j + 1);
                    }
                }
            }
        }
    }

    // write lists to global (coalesced)
    __syncthreads();
    for (int i = tid; i < TM; i += 256) g_cnt[n0 + i] = sCnt[i];
    {
        const uint32_t* cu = (const uint32_t*)sCand;
        uint32_t* gu = (uint32_t*)g_cand + (size_t)n0 * (KCAND / 2);
        for (int i = tid; i < TM * (KCAND / 2); i += 256) gu[i] = cu[i];
    }
}

// ---------------------------------------------------------------------------
// Kernel 3 (pass 2): exact argmin over candidate lists, 4-way ILP rescore.
// ---------------------------------------------------------------------------
__global__ void __launch_bounds__(256) argmin_kernel(const float* __restrict__ z,
                                                     const float* __restrict__ cb,
                                                     float* __restrict__ dout) {
    __shared__ float zs[32][260];
    const int tid  = threadIdx.x;
    const int w    = tid >> 5;
    const int lane = tid & 31;

    const int n0  = blockIdx.x * 32;
    const int b   = n0 >> 12;
    const int hw0 = n0 & (HW - 1);

    for (int i = tid; i < D * 32 / 4; i += 256) {
        int k  = i >> 3;
        int t4 = (i & 7) * 4;
        float4 v = *(const float4*)(z + (size_t)b * CC * HW + (size_t)k * HW + hw0 + t4);
        zs[t4 + 0][k] = v.x; zs[t4 + 1][k] = v.y;
        zs[t4 + 2][k] = v.z; zs[t4 + 3][k] = v.w;
    }
    __syncthreads();

    for (int tt = 0; tt < 4; tt++) {
        const int t = w * 4 + tt;
        const int n = n0 + t;
        const int cnt = g_cnt[n];

        float best = 3.4e38f;
        int   bi   = 0;
        if (cnt <= KCAND) {
            const unsigned short* lst = g_cand + (size_t)n * KCAND;
            int ci = 0;
            for (; ci + 4 <= cnt; ci += 4) {
                int j0 = lst[ci], j1 = lst[ci + 1], j2 = lst[ci + 2], j3 = lst[ci + 3];
                const float* c0 = cb + (size_t)j0 * D;
                const float* c1 = cb + (size_t)j1 * D;
                const float* c2 = cb + (size_t)j2 * D;
                const float* c3 = cb + (size_t)j3 * D;
                float s0 = 0.f, s1 = 0.f, s2 = 0.f, s3 = 0.f;
                #pragma unroll
                for (int u = 0; u < 8; u++) {
                    float zv = zs[t][lane + 32 * u];
                    s0 = fmaf(zv, c0[lane + 32 * u], s0);
                    s1 = fmaf(zv, c1[lane + 32 * u], s1);
                    s2 = fmaf(zv, c2[lane + 32 * u], s2);
                    s3 = fmaf(zv, c3[lane + 32 * u], s3);
                }
                #pragma unroll
                for (int o = 16; o; o >>= 1) s0 += __shfl_xor_sync(0xffffffffu, s0, o);
                #pragma unroll
                for (int o = 16; o; o >>= 1) s1 += __shfl_xor_sync(0xffffffffu, s1, o);
                #pragma unroll
                for (int o = 16; o; o >>= 1) s2 += __shfl_xor_sync(0xffffffffu, s2, o);
                #pragma unroll
                for (int o = 16; o; o >>= 1) s3 += __shfl_xor_sync(0xffffffffu, s3, o);
                float d0 = g_cnorm[j0] - 2.0f * s0;
                float d1 = g_cnorm[j1] - 2.0f * s1;
                float d2 = g_cnorm[j2] - 2.0f * s2;
                float d3 = g_cnorm[j3] - 2.0f * s3;
                if (d0 < best || (d0 == best && j0 < bi)) { best = d0; bi = j0; }
                if (d1 < best || (d1 == best && j1 < bi)) { best = d1; bi = j1; }
                if (d2 < best || (d2 == best && j2 < bi)) { best = d2; bi = j2; }
                if (d3 < best || (d3 == best && j3 < bi)) { best = d3; bi = j3; }
            }
            for (; ci < cnt; ci++) {
                int j = lst[ci];
                const float* crow = cb + (size_t)j * D;
                float s = 0.f;
                #pragma unroll
                for (int u = 0; u < 8; u++)
                    s = fmaf(zs[t][lane + 32 * u], crow[lane + 32 * u], s);
                #pragma unroll
                for (int o = 16; o; o >>= 1) s += __shfl_xor_sync(0xffffffffu, s, o);
                float dist = g_cnorm[j] - 2.0f * s;
                if (dist < best || (dist == best && j < bi)) { best = dist; bi = j; }
            }
        } else {
            for (int j = 0; j < NE; j++) {
                const float* crow = cb + (size_t)j * D;
                float s = 0.f;
                #pragma unroll
                for (int u = 0; u < 8; u++)
                    s = fmaf(zs[t][lane + 32 * u], crow[lane + 32 * u], s);
                #pragma unroll
                for (int o = 16; o; o >>= 1) s += __shfl_xor_sync(0xffffffffu, s, o);
                float dist = g_cnorm[j] - 2.0f * s;
                if (dist < best) { best = dist; bi = j; }
            }
        }
        if (lane == 0) {
            g_idx[n] = bi;
            dout[IDX_OFF + n] = (float)bi;
        }
    }
}

// ---------------------------------------------------------------------------
// Kernel 4: gather (R13-measured 39.8us version)
// ---------------------------------------------------------------------------
#define GTOK 32
__global__ void __launch_bounds__(256) gather_kernel(const float* __restrict__ z,
                                                     const float* __restrict__ cb,
                                                     float* __restrict__ dout) {
    __shared__ float zq[GTOK][257];
    __shared__ int   idxs[GTOK];
    __shared__ float ws[8];

    const int tid = threadIdx.x;
    const int n0  = blockIdx.x * GTOK;
    const int b   = n0 / HW;
    const int hw0 = n0 % HW;

    if (tid < GTOK) idxs[tid] = g_idx[n0 + tid];
    __syncthreads();

    #pragma unroll 4
    for (int t = 0; t < GTOK; t++) {
        zq[t][tid] = cb[(size_t)idxs[t] * D + tid];
    }
    __syncthreads();

    const int t  = tid & 31;
    const int c0 = tid >> 5;
    float s = 0.f;
    const float* zb = z    + (size_t)b * CC * HW + hw0 + t;
    float*       ob = dout + (size_t)b * CC * HW + hw0 + t;
    #pragma unroll 8
    for (int it = 0; it < 32; it++) {
        int c = c0 * 32 + it;
        float zv = zb[(size_t)c * HW];
        float d  = zq[t][c] - zv;
        ob[(size_t)c * HW] = zv + d;   // z + sg(z_q - z), exact fp32 expr
        s = fmaf(d, d, s);
    }

    #pragma unroll
    for (int o = 16; o; o >>= 1) s += __shfl_xor_sync(0xffffffffu, s, o);
    if ((tid & 31) == 0) ws[tid >> 5] = s;
    __syncthreads();
    if (tid < 8) {
        float v = ws[tid];
        #pragma unroll
        for (int o = 4; o; o >>= 1) v += __shfl_xor_sync(0xffu, v, o);
        if (tid == 0) g_partial[blockIdx.x] = v;
    }
}

// ---------------------------------------------------------------------------
// Kernel 5: deterministic final reduction
// ---------------------------------------------------------------------------
__global__ void __launch_bounds__(256) finalize_kernel(float* __restrict__ dout) {
    __shared__ float sh[256];
    float s = 0.f;
    for (int i = threadIdx.x; i < GRID_C; i += 256) s += g_partial[i];
    sh[threadIdx.x] = s;
    __syncthreads();
    for (int o = 128; o; o >>= 1) {
        if (threadIdx.x < o) sh[threadIdx.x] += sh[threadIdx.x + o];
        __syncthreads();
    }
    if (threadIdx.x == 0) {
        dout[LOSS_OFF] = sh[0] * (2.0f / (float)ZQ_ELEMS);
        dout[CLS_OFF]  = 0.0f;
    }
}

// ---------------------------------------------------------------------------
extern "C" void kernel_launch(void* const* d_in, const int* in_sizes, int n_in,
                              void* d_out, int out_size) {
    const float* z  = (const float*)d_in[0];   // [B,C,H,W] fp32
    const float* cb = (const float*)d_in[1];   // [NE, D]   fp32
    float* out = (float*)d_out;

    cudaFuncSetAttribute(dist_kernel,
                         cudaFuncAttributeMaxDynamicSharedMemorySize, P1_SMEM);

    cnorm_kernel <<<NE / 8, 256>>>(cb);
    dist_kernel  <<<NTOK / TM, 256, P1_SMEM>>>(z);
    argmin_kernel<<<NTOK / 32, 256>>>(z, cb, out);
    gather_kernel<<<NTOK / GTOK, 256>>>(z, cb, out);
    finalize_kernel<<<1, 256>>>(out);
}